// round 1
// baseline (speedup 1.0000x reference)
#include <cuda_runtime.h>
#include <cuda_bf16.h>

#define T_STEPS 32768
#define IN_SIZE 1024
#define HID     64
#define GATES   256   // 4 * HID

// Scratch: precomputed input projection, (T, 4H) row-major. 33.5 MB static.
__device__ float g_xproj[T_STEPS * GATES];

// ---------------------------------------------------------------------------
// Kernel 1: x_proj[t][j] = sum_k spec[k][t] * W_ih[j][k] + b_ih[j] + b_hh[j]
// Tiled FP32 GEMM: block = 64 timesteps x 256 gates, BK = 8, 256 threads,
// each thread computes an 8x8 (t x j) micro-tile.
// ---------------------------------------------------------------------------
__global__ void __launch_bounds__(256, 1)
gemm_xproj_kernel(const float* __restrict__ spec,
                  const float* __restrict__ W_ih,
                  const float* __restrict__ b_ih,
                  const float* __restrict__ b_hh)
{
    __shared__ float sS[8][64];    // [kk][t]
    __shared__ float sW[8][GATES]; // [kk][j]

    const int tid = threadIdx.x;
    const int t0  = blockIdx.x * 64;
    const int tj  = (tid & 31) * 8;  // j base for this thread (0..248)
    const int tt  = (tid >> 5) * 8;  // t base within tile (0..56)

    float acc[8][8];
#pragma unroll
    for (int i = 0; i < 8; i++)
#pragma unroll
        for (int j = 0; j < 8; j++) acc[i][j] = 0.f;

    const int krow = tid >> 6;   // 0..3
    const int tcol = tid & 63;   // 0..63

    for (int k0 = 0; k0 < IN_SIZE; k0 += 8) {
        // Load spec tile: 8 x 64, coalesced along t
        sS[krow][tcol]     = spec[(k0 + krow) * T_STEPS + t0 + tcol];
        sS[krow + 4][tcol] = spec[(k0 + krow + 4) * T_STEPS + t0 + tcol];
        // Load W tile: thread tid loads row j = tid, k0..k0+7 (two float4)
        float4 wa = *reinterpret_cast<const float4*>(W_ih + (size_t)tid * IN_SIZE + k0);
        float4 wb = *reinterpret_cast<const float4*>(W_ih + (size_t)tid * IN_SIZE + k0 + 4);
        sW[0][tid] = wa.x; sW[1][tid] = wa.y; sW[2][tid] = wa.z; sW[3][tid] = wa.w;
        sW[4][tid] = wb.x; sW[5][tid] = wb.y; sW[6][tid] = wb.z; sW[7][tid] = wb.w;
        __syncthreads();

#pragma unroll
        for (int kk = 0; kk < 8; kk++) {
            float4 s0 = *reinterpret_cast<const float4*>(&sS[kk][tt]);
            float4 s1 = *reinterpret_cast<const float4*>(&sS[kk][tt + 4]);
            float4 w0 = *reinterpret_cast<const float4*>(&sW[kk][tj]);
            float4 w1 = *reinterpret_cast<const float4*>(&sW[kk][tj + 4]);
            float sv[8] = {s0.x, s0.y, s0.z, s0.w, s1.x, s1.y, s1.z, s1.w};
            float wv[8] = {w0.x, w0.y, w0.z, w0.w, w1.x, w1.y, w1.z, w1.w};
#pragma unroll
            for (int i = 0; i < 8; i++)
#pragma unroll
                for (int j = 0; j < 8; j++)
                    acc[i][j] = fmaf(sv[i], wv[j], acc[i][j]);
        }
        __syncthreads();
    }

    // Epilogue: add bias, store (vectorized float4)
    float bias[8];
#pragma unroll
    for (int j = 0; j < 8; j++) bias[j] = b_ih[tj + j] + b_hh[tj + j];

#pragma unroll
    for (int i = 0; i < 8; i++) {
        const int t = t0 + tt + i;
        float4 o0, o1;
        o0.x = acc[i][0] + bias[0]; o0.y = acc[i][1] + bias[1];
        o0.z = acc[i][2] + bias[2]; o0.w = acc[i][3] + bias[3];
        o1.x = acc[i][4] + bias[4]; o1.y = acc[i][5] + bias[5];
        o1.z = acc[i][6] + bias[6]; o1.w = acc[i][7] + bias[7];
        *reinterpret_cast<float4*>(&g_xproj[(size_t)t * GATES + tj])     = o0;
        *reinterpret_cast<float4*>(&g_xproj[(size_t)t * GATES + tj + 4]) = o1;
    }
}

// ---------------------------------------------------------------------------
// Fast activations (MUFU-based). Clamp tanh arg: avoids inf/inf -> NaN and
// matches the saturated value (1.0) exactly.
// ---------------------------------------------------------------------------
__device__ __forceinline__ float fast_sigmoid(float x) {
    return __fdividef(1.f, 1.f + __expf(-x));
}
__device__ __forceinline__ float fast_tanh(float x) {
    x = fminf(fmaxf(x, -15.f), 15.f);
    float e = __expf(2.f * x);
    return __fdividef(e - 1.f, e + 1.f);
}

// ---------------------------------------------------------------------------
// Kernel 2: sequential LSTM over 32768 steps, single block of 256 threads.
// Thread j owns gate row j: W_hh[j][0..63] lives in registers (fully
// unrolled dot product). h broadcast via shared memory. Gate order: i,f,g,o.
// Finishes with log_softmax over final h -> out[0..63].
// ---------------------------------------------------------------------------
__global__ void __launch_bounds__(256, 1)
lstm_seq_kernel(const float* __restrict__ W_hh, float* __restrict__ out)
{
    __shared__ float h_sh[HID];
    __shared__ float act[GATES];

    const int tid = threadIdx.x;

    // Load this thread's weight row into registers
    float w[HID];
#pragma unroll
    for (int k = 0; k < HID; k += 4) {
        float4 v = *reinterpret_cast<const float4*>(W_hh + (size_t)tid * HID + k);
        w[k] = v.x; w[k + 1] = v.y; w[k + 2] = v.z; w[k + 3] = v.w;
    }

    float c = 0.f;
    if (tid < HID) h_sh[tid] = 0.f;

    float xn = g_xproj[tid];  // x_proj for t = 0
    const int group = tid >> 6;  // 0:i 1:f 2:g 3:o
    __syncthreads();

    for (int t = 0; t < T_STEPS; t++) {
        const float xc = xn;
        // Prefetch next step's x_proj (hides L2/DRAM latency behind the matvec)
        const int tn = (t + 1 < T_STEPS) ? (t + 1) : t;
        xn = g_xproj[(size_t)tn * GATES + tid];

        // Dot product: gates_pre[j] = x_proj + sum_k h[k] * W_hh[j][k]
        float s0 = 0.f, s1 = 0.f, s2 = 0.f, s3 = 0.f;
#pragma unroll
        for (int k = 0; k < HID; k += 8) {
            float4 h0 = *reinterpret_cast<const float4*>(&h_sh[k]);
            float4 h1 = *reinterpret_cast<const float4*>(&h_sh[k + 4]);
            s0 = fmaf(h0.x, w[k],     s0);
            s1 = fmaf(h0.y, w[k + 1], s1);
            s2 = fmaf(h0.z, w[k + 2], s2);
            s3 = fmaf(h0.w, w[k + 3], s3);
            s0 = fmaf(h1.x, w[k + 4], s0);
            s1 = fmaf(h1.y, w[k + 5], s1);
            s2 = fmaf(h1.z, w[k + 6], s2);
            s3 = fmaf(h1.w, w[k + 7], s3);
        }
        const float a = xc + ((s0 + s1) + (s2 + s3));

        // Per-gate nonlinearity: g-gate (group 2) = tanh, others = sigmoid
        act[tid] = (group == 2) ? fast_tanh(a) : fast_sigmoid(a);
        __syncthreads();

        if (tid < HID) {
            // c = sig(f)*c + sig(i)*tanh(g);  h = sig(o)*tanh(c)
            c = act[HID + tid] * c + act[tid] * act[2 * HID + tid];
            h_sh[tid] = act[3 * HID + tid] * fast_tanh(c);
        }
        __syncthreads();
    }

    // log_softmax over final h (accurate libm versions; runs once)
    if (tid < HID) {
        float m = -1e30f;
#pragma unroll 8
        for (int k = 0; k < HID; k++) m = fmaxf(m, h_sh[k]);
        float sum = 0.f;
#pragma unroll 8
        for (int k = 0; k < HID; k++) sum += expf(h_sh[k] - m);
        out[tid] = h_sh[tid] - m - logf(sum);
    }
}

// ---------------------------------------------------------------------------
// Launch: inputs in metadata order: spectrogram, W_ih, W_hh, b_ih, b_hh
// ---------------------------------------------------------------------------
extern "C" void kernel_launch(void* const* d_in, const int* in_sizes, int n_in,
                              void* d_out, int out_size)
{
    const float* spec = (const float*)d_in[0];
    const float* W_ih = (const float*)d_in[1];
    const float* W_hh = (const float*)d_in[2];
    const float* b_ih = (const float*)d_in[3];
    const float* b_hh = (const float*)d_in[4];
    float* out = (float*)d_out;

    gemm_xproj_kernel<<<T_STEPS / 64, 256>>>(spec, W_ih, b_ih, b_hh);
    lstm_seq_kernel<<<1, 256>>>(W_hh, out);
}

// round 2
// speedup vs baseline: 1.0528x; 1.0528x over previous
#include <cuda_runtime.h>
#include <cuda_bf16.h>

#define T_STEPS 32768
#define IN_SIZE 1024
#define HID     64
#define GATES   256   // 4 * HID

// Scratch: precomputed input projection, (T, 4H) row-major. 33.5 MB static.
__device__ float g_xproj[T_STEPS * GATES];

// ---------------------------------------------------------------------------
// Kernel 1: x_proj[t][j] = sum_k spec[k][t] * W_ih[j][k] + b_ih[j] + b_hh[j]
// Tiled FP32 GEMM: block = 64 timesteps x 256 gates, BK = 8, 256 threads,
// each thread computes an 8x8 (t x j) micro-tile.
// ---------------------------------------------------------------------------
__global__ void __launch_bounds__(256, 1)
gemm_xproj_kernel(const float* __restrict__ spec,
                  const float* __restrict__ W_ih,
                  const float* __restrict__ b_ih,
                  const float* __restrict__ b_hh)
{
    __shared__ float sS[8][64];    // [kk][t]
    __shared__ float sW[8][GATES]; // [kk][j]

    const int tid = threadIdx.x;
    const int t0  = blockIdx.x * 64;
    const int tj  = (tid & 31) * 8;  // j base for this thread (0..248)
    const int tt  = (tid >> 5) * 8;  // t base within tile (0..56)

    float acc[8][8];
#pragma unroll
    for (int i = 0; i < 8; i++)
#pragma unroll
        for (int j = 0; j < 8; j++) acc[i][j] = 0.f;

    const int krow = tid >> 6;   // 0..3
    const int tcol = tid & 63;   // 0..63

    for (int k0 = 0; k0 < IN_SIZE; k0 += 8) {
        sS[krow][tcol]     = spec[(k0 + krow) * T_STEPS + t0 + tcol];
        sS[krow + 4][tcol] = spec[(k0 + krow + 4) * T_STEPS + t0 + tcol];
        float4 wa = *reinterpret_cast<const float4*>(W_ih + (size_t)tid * IN_SIZE + k0);
        float4 wb = *reinterpret_cast<const float4*>(W_ih + (size_t)tid * IN_SIZE + k0 + 4);
        sW[0][tid] = wa.x; sW[1][tid] = wa.y; sW[2][tid] = wa.z; sW[3][tid] = wa.w;
        sW[4][tid] = wb.x; sW[5][tid] = wb.y; sW[6][tid] = wb.z; sW[7][tid] = wb.w;
        __syncthreads();

#pragma unroll
        for (int kk = 0; kk < 8; kk++) {
            float4 s0 = *reinterpret_cast<const float4*>(&sS[kk][tt]);
            float4 s1 = *reinterpret_cast<const float4*>(&sS[kk][tt + 4]);
            float4 w0 = *reinterpret_cast<const float4*>(&sW[kk][tj]);
            float4 w1 = *reinterpret_cast<const float4*>(&sW[kk][tj + 4]);
            float sv[8] = {s0.x, s0.y, s0.z, s0.w, s1.x, s1.y, s1.z, s1.w};
            float wv[8] = {w0.x, w0.y, w0.z, w0.w, w1.x, w1.y, w1.z, w1.w};
#pragma unroll
            for (int i = 0; i < 8; i++)
#pragma unroll
                for (int j = 0; j < 8; j++)
                    acc[i][j] = fmaf(sv[i], wv[j], acc[i][j]);
        }
        __syncthreads();
    }

    float bias[8];
#pragma unroll
    for (int j = 0; j < 8; j++) bias[j] = b_ih[tj + j] + b_hh[tj + j];

#pragma unroll
    for (int i = 0; i < 8; i++) {
        const int t = t0 + tt + i;
        float4 o0, o1;
        o0.x = acc[i][0] + bias[0]; o0.y = acc[i][1] + bias[1];
        o0.z = acc[i][2] + bias[2]; o0.w = acc[i][3] + bias[3];
        o1.x = acc[i][4] + bias[4]; o1.y = acc[i][5] + bias[5];
        o1.z = acc[i][6] + bias[6]; o1.w = acc[i][7] + bias[7];
        *reinterpret_cast<float4*>(&g_xproj[(size_t)t * GATES + tj])     = o0;
        *reinterpret_cast<float4*>(&g_xproj[(size_t)t * GATES + tj + 4]) = o1;
    }
}

// ---------------------------------------------------------------------------
// Fast activations. Overflow-safe without clamps:
//   sigmoid(x) = 1 / (1 + e^-x)       (x -> -inf: exp=inf -> rcp -> 0)
//   tanh(x)    = 2*sigmoid(2x) - 1    (saturates to +/-1 cleanly)
// ---------------------------------------------------------------------------
__device__ __forceinline__ float sigm(float x) {
    return __fdividef(1.f, 1.f + __expf(-x));
}

// Packed f32x2 FMA: acc = a * b + acc  (2 MACs per instruction, fma pipe)
__device__ __forceinline__ void ffma2(unsigned long long& acc,
                                      unsigned long long a,
                                      unsigned long long b) {
    asm("fma.rn.f32x2 %0, %1, %2, %0;" : "+l"(acc) : "l"(a), "l"(b));
}
__device__ __forceinline__ float2 unpack2(unsigned long long v) {
    float2 r;
    asm("mov.b64 {%0, %1}, %2;" : "=f"(r.x), "=f"(r.y) : "l"(v));
    return r;
}

// ---------------------------------------------------------------------------
// Kernel 2: sequential LSTM, single block of 256 threads.
// Thread layout: unit u = tid>>2, gate = tid&3 (0:i 1:f 2:g 3:o).
// All 4 gates of a unit live in adjacent lanes of one warp -> activation
// exchange via shfl.idx, no barrier. Double-buffered h_sh -> ONE
// __syncthreads per step. Matvec uses packed fma.rn.f32x2 (FFMA2).
// ---------------------------------------------------------------------------
__global__ void __launch_bounds__(256, 1)
lstm_seq_kernel(const float* __restrict__ W_hh, float* __restrict__ out)
{
    __shared__ __align__(16) float h_sh[2][HID];

    const int tid  = threadIdx.x;
    const int u    = tid >> 2;        // hidden unit 0..63
    const int gate = tid & 3;         // 0:i 1:f 2:g 3:o
    const int lane = tid & 31;
    const int lbase = lane & ~3;      // first lane of this unit's 4-lane group
    const int row  = gate * HID + u;  // W_hh / x_proj row for this thread

    // Load weight row as 32 packed f32 pairs (64 regs)
    unsigned long long wq[HID / 2];
    {
        const ulonglong2* wp =
            reinterpret_cast<const ulonglong2*>(W_hh + (size_t)row * HID);
#pragma unroll
        for (int i = 0; i < HID / 8; i++) {       // 8 x ulonglong2 = 64 floats
            ulonglong2 v0 = wp[2 * i];
            ulonglong2 v1 = wp[2 * i + 1];
            wq[4 * i]     = v0.x; wq[4 * i + 1] = v0.y;
            wq[4 * i + 2] = v1.x; wq[4 * i + 3] = v1.y;
        }
    }

    // Activation constants: gate g uses tanh(a) = 2*sigm(2a) - 1
    const float amul = (gate == 2) ? 2.f : 1.f;
    const float aoff = (gate == 2) ? -1.f : 0.f;

    float c = 0.f;
    if (tid < HID) { h_sh[0][tid] = 0.f; }

    float xn = g_xproj[row];   // x_proj for t = 0
    __syncthreads();

    for (int t = 0; t < T_STEPS; t++) {
        const int rbuf = t & 1;
        const float xc = xn;
        const int tn = (t + 1 < T_STEPS) ? (t + 1) : t;
        xn = g_xproj[(size_t)tn * GATES + row];   // prefetch next step

        // a = x_proj + h . W_hh[row]  (packed FFMA2, 32 instructions)
        unsigned long long a0 = 0ull, a1 = 0ull, a2 = 0ull, a3 = 0ull;
        const ulonglong2* hp =
            reinterpret_cast<const ulonglong2*>(&h_sh[rbuf][0]);
#pragma unroll
        for (int k = 0; k < HID / 8; k++) {       // 8 iterations
            ulonglong2 hA = hp[2 * k];
            ulonglong2 hB = hp[2 * k + 1];
            ffma2(a0, hA.x, wq[4 * k]);
            ffma2(a1, hA.y, wq[4 * k + 1]);
            ffma2(a2, hB.x, wq[4 * k + 2]);
            ffma2(a3, hB.y, wq[4 * k + 3]);
        }
        float2 f0 = unpack2(a0), f1 = unpack2(a1);
        float2 f2 = unpack2(a2), f3 = unpack2(a3);
        const float a = xc + (((f0.x + f0.y) + (f1.x + f1.y)) +
                              ((f2.x + f2.y) + (f3.x + f3.y)));

        // Own gate activation (sigmoid, or tanh for gate==2 via 2*sigm(2a)-1)
        const float act = fmaf(amul, sigm(amul * a), aoff);

        // Exchange the 4 gate activations within the 4-lane group
        const float i_a = __shfl_sync(0xffffffffu, act, lbase + 0);
        const float f_a = __shfl_sync(0xffffffffu, act, lbase + 1);
        const float g_a = __shfl_sync(0xffffffffu, act, lbase + 2);
        const float o_a = __shfl_sync(0xffffffffu, act, lbase + 3);

        // All 4 lanes of the group redundantly update c and h (identical)
        c = fmaf(f_a, c, i_a * g_a);
        const float th = fmaf(2.f, sigm(c + c), -1.f);   // tanh(c)
        if (gate == 0) h_sh[rbuf ^ 1][u] = o_a * th;

        __syncthreads();
    }

    // log_softmax over final h (accurate libm versions; runs once).
    // Final h lives in buffer (T_STEPS & 1) = 0.
    if (tid < HID) {
        const float* hf = h_sh[T_STEPS & 1];
        float m = -1e30f;
#pragma unroll 8
        for (int k = 0; k < HID; k++) m = fmaxf(m, hf[k]);
        float sum = 0.f;
#pragma unroll 8
        for (int k = 0; k < HID; k++) sum += expf(hf[k] - m);
        out[tid] = hf[tid] - m - logf(sum);
    }
}

// ---------------------------------------------------------------------------
// Launch: inputs in metadata order: spectrogram, W_ih, W_hh, b_ih, b_hh
// ---------------------------------------------------------------------------
extern "C" void kernel_launch(void* const* d_in, const int* in_sizes, int n_in,
                              void* d_out, int out_size)
{
    const float* spec = (const float*)d_in[0];
    const float* W_ih = (const float*)d_in[1];
    const float* W_hh = (const float*)d_in[2];
    const float* b_ih = (const float*)d_in[3];
    const float* b_hh = (const float*)d_in[4];
    float* out = (float*)d_out;

    gemm_xproj_kernel<<<T_STEPS / 64, 256>>>(spec, W_ih, b_ih, b_hh);
    lstm_seq_kernel<<<1, 256>>>(W_hh, out);
}